// round 1
// baseline (speedup 1.0000x reference)
#include <cuda_runtime.h>
#include <cstdint>

#define IMG_N   4096
#define OUT_N   4094
#define TILE_W  256
#define TILE_H  32
#define THREADS 128
#define IN_W    258   // TILE_W + 2 halo
#define IN_H    34    // TILE_H + 2 halo
#define SSTRIDE 264   // padded row stride (floats)

__global__ __launch_bounds__(THREADS)
void conv3x3_kernel(const float* __restrict__ X,
                    const float* __restrict__ W,
                    const float* __restrict__ B,
                    float* __restrict__ out)
{
    __shared__ float s[IN_H * SSTRIDE];

    const int tid  = threadIdx.x;
    const int col0 = blockIdx.x * TILE_W;   // input & output col origin (valid conv)
    const int row0 = blockIdx.y * TILE_H;   // input & output row origin

    // ---- weights + bias (broadcast loads, L1-resident) ----
    const float w00 = W[0], w01 = W[1], w02 = W[2];
    const float w10 = W[3], w11 = W[4], w12 = W[5];
    const float w20 = W[6], w21 = W[7], w22 = W[8];
    const float bias = B[0];

    // ---- load input tile: rows [row0, row0+34), cols [col0, col0+258) ----
    // Main body: cols [0,256) as 64 float4 per row -> always in-bounds in x
    // (col0 <= 3840, col0+255 = 4095). Only row guard needed.
    {
        const int total4 = IN_H * 64;                 // 2176 float4 slots
        for (int i = tid; i < total4; i += THREADS) {
            const int r  = i >> 6;                    // row within tile
            const int c4 = i & 63;                    // float4 index within row
            const int gr = row0 + r;
            float4 v = make_float4(0.f, 0.f, 0.f, 0.f);
            if (gr < IMG_N) {
                v = *reinterpret_cast<const float4*>(
                        X + (size_t)gr * IMG_N + col0 + (c4 << 2));
            }
            *reinterpret_cast<float4*>(&s[r * SSTRIDE + (c4 << 2)]) = v;
        }
        // Tail: cols 256,257 (may run off the right edge on last block-x)
        const int totalT = IN_H * 2;                  // 68 scalars
        for (int i = tid; i < totalT; i += THREADS) {
            const int r  = i >> 1;
            const int c  = 256 + (i & 1);
            const int gr = row0 + r;
            const int gc = col0 + c;
            float v = 0.f;
            if (gr < IMG_N && gc < IMG_N)
                v = X[(size_t)gr * IMG_N + gc];
            s[r * SSTRIDE + c] = v;
        }
    }
    __syncthreads();

    // ---- compute: each thread owns 2 adjacent output columns, rolls 3 rows ----
    const int c = tid * 2;                    // smem col base; needs cols c..c+3
    const int ocol = col0 + c;
    const bool colok = (ocol < OUT_N);        // ocol even, OUT_N even => ocol+1 ok too

    float x0[4], x1[4], x2[4];
    {
        float2 a = *reinterpret_cast<const float2*>(&s[0 * SSTRIDE + c]);
        float2 b = *reinterpret_cast<const float2*>(&s[0 * SSTRIDE + c + 2]);
        x0[0] = a.x; x0[1] = a.y; x0[2] = b.x; x0[3] = b.y;
        a = *reinterpret_cast<const float2*>(&s[1 * SSTRIDE + c]);
        b = *reinterpret_cast<const float2*>(&s[1 * SSTRIDE + c + 2]);
        x1[0] = a.x; x1[1] = a.y; x1[2] = b.x; x1[3] = b.y;
    }

    #pragma unroll
    for (int r = 0; r < TILE_H; ++r) {
        float2 a = *reinterpret_cast<const float2*>(&s[(r + 2) * SSTRIDE + c]);
        float2 b = *reinterpret_cast<const float2*>(&s[(r + 2) * SSTRIDE + c + 2]);
        x2[0] = a.x; x2[1] = a.y; x2[2] = b.x; x2[3] = b.y;

        float o0 = bias;
        o0 = fmaf(w00, x0[0], o0); o0 = fmaf(w01, x0[1], o0); o0 = fmaf(w02, x0[2], o0);
        o0 = fmaf(w10, x1[0], o0); o0 = fmaf(w11, x1[1], o0); o0 = fmaf(w12, x1[2], o0);
        o0 = fmaf(w20, x2[0], o0); o0 = fmaf(w21, x2[1], o0); o0 = fmaf(w22, x2[2], o0);

        float o1 = bias;
        o1 = fmaf(w00, x0[1], o1); o1 = fmaf(w01, x0[2], o1); o1 = fmaf(w02, x0[3], o1);
        o1 = fmaf(w10, x1[1], o1); o1 = fmaf(w11, x1[2], o1); o1 = fmaf(w12, x1[3], o1);
        o1 = fmaf(w20, x2[1], o1); o1 = fmaf(w21, x2[2], o1); o1 = fmaf(w22, x2[3], o1);

        const int orow = row0 + r;
        if (colok && orow < OUT_N) {
            *reinterpret_cast<float2*>(out + (size_t)orow * OUT_N + ocol) =
                make_float2(o0, o1);
        }

        #pragma unroll
        for (int j = 0; j < 4; ++j) { x0[j] = x1[j]; x1[j] = x2[j]; }
    }
}

extern "C" void kernel_launch(void* const* d_in, const int* in_sizes, int n_in,
                              void* d_out, int out_size)
{
    const float* X = (const float*)d_in[0];   // 4096*4096
    const float* W = (const float*)d_in[1];   // 9
    const float* B = (const float*)d_in[2];   // 1
    float* out = (float*)d_out;               // 4094*4094

    dim3 grid((OUT_N + TILE_W - 1) / TILE_W,   // 16
              (OUT_N + TILE_H - 1) / TILE_H);  // 128
    conv3x3_kernel<<<grid, THREADS>>>(X, W, B, out);
}

// round 2
// speedup vs baseline: 1.6794x; 1.6794x over previous
#include <cuda_runtime.h>
#include <cstdint>

#define IMG_N   4096
#define OUT_N   4094
#define THREADS 256
#define T_ROWS  8          // output rows per thread
#define T_COLS  4          // output cols per thread

__device__ __forceinline__ void load_row(const float* __restrict__ X,
                                         int ir, int ocol, float* dst)
{
    if (ir < IMG_N) {
        float4 L = *reinterpret_cast<const float4*>(X + (size_t)ir * IMG_N + ocol);
        dst[0] = L.x; dst[1] = L.y; dst[2] = L.z; dst[3] = L.w;
        if (ocol + 7 < IMG_N) {
            float4 R = *reinterpret_cast<const float4*>(X + (size_t)ir * IMG_N + ocol + 4);
            dst[4] = R.x; dst[5] = R.y; dst[6] = R.z; dst[7] = R.w;
        } else {
            dst[4] = dst[5] = dst[6] = dst[7] = 0.f;
        }
    } else {
        #pragma unroll
        for (int j = 0; j < 8; ++j) dst[j] = 0.f;
    }
}

__global__ __launch_bounds__(THREADS)
void conv3x3_kernel(const float* __restrict__ X,
                    const float* __restrict__ W,
                    const float* __restrict__ B,
                    float* __restrict__ out)
{
    const int tid   = threadIdx.x;
    const int ocol  = (blockIdx.x * THREADS + tid) * T_COLS;  // 0..4092, mult of 4
    const int orow0 = blockIdx.y * T_ROWS;

    const float w00 = W[0], w01 = W[1], w02 = W[2];
    const float w10 = W[3], w11 = W[4], w12 = W[5];
    const float w20 = W[6], w21 = W[7], w22 = W[8];
    const float bias = B[0];

    float a[8], b[8], c[8];
    load_row(X, orow0,     ocol, a);
    load_row(X, orow0 + 1, ocol, b);

    #pragma unroll
    for (int r = 0; r < T_ROWS; ++r) {
        load_row(X, orow0 + r + 2, ocol, c);

        float o0 = bias, o1 = bias, o2 = bias, o3 = bias;
        #pragma unroll
        for (int j = 0; j < 1; ++j) { /* keep structure flat */ }

        o0 = fmaf(w00, a[0], o0); o0 = fmaf(w01, a[1], o0); o0 = fmaf(w02, a[2], o0);
        o0 = fmaf(w10, b[0], o0); o0 = fmaf(w11, b[1], o0); o0 = fmaf(w12, b[2], o0);
        o0 = fmaf(w20, c[0], o0); o0 = fmaf(w21, c[1], o0); o0 = fmaf(w22, c[2], o0);

        o1 = fmaf(w00, a[1], o1); o1 = fmaf(w01, a[2], o1); o1 = fmaf(w02, a[3], o1);
        o1 = fmaf(w10, b[1], o1); o1 = fmaf(w11, b[2], o1); o1 = fmaf(w12, b[3], o1);
        o1 = fmaf(w20, c[1], o1); o1 = fmaf(w21, c[2], o1); o1 = fmaf(w22, c[3], o1);

        o2 = fmaf(w00, a[2], o2); o2 = fmaf(w01, a[3], o2); o2 = fmaf(w02, a[4], o2);
        o2 = fmaf(w10, b[2], o2); o2 = fmaf(w11, b[3], o2); o2 = fmaf(w12, b[4], o2);
        o2 = fmaf(w20, c[2], o2); o2 = fmaf(w21, c[3], o2); o2 = fmaf(w22, c[4], o2);

        o3 = fmaf(w00, a[3], o3); o3 = fmaf(w01, a[4], o3); o3 = fmaf(w02, a[5], o3);
        o3 = fmaf(w10, b[3], o3); o3 = fmaf(w11, b[4], o3); o3 = fmaf(w12, b[5], o3);
        o3 = fmaf(w20, c[3], o3); o3 = fmaf(w21, c[4], o3); o3 = fmaf(w22, c[5], o3);

        const int orow = orow0 + r;
        if (orow < OUT_N && ocol < OUT_N) {
            float* p = out + (size_t)orow * OUT_N + ocol;   // 8B-aligned always
            *reinterpret_cast<float2*>(p) = make_float2(o0, o1);
            if (ocol + 2 < OUT_N)
                *reinterpret_cast<float2*>(p + 2) = make_float2(o2, o3);
        }

        #pragma unroll
        for (int j = 0; j < 8; ++j) { a[j] = b[j]; b[j] = c[j]; }
    }
}

extern "C" void kernel_launch(void* const* d_in, const int* in_sizes, int n_in,
                              void* d_out, int out_size)
{
    const float* X = (const float*)d_in[0];   // 4096*4096
    const float* W = (const float*)d_in[1];   // 9
    const float* B = (const float*)d_in[2];   // 1
    float* out = (float*)d_out;               // 4094*4094

    dim3 grid(IMG_N / (THREADS * T_COLS),                 // 4
              (OUT_N + T_ROWS - 1) / T_ROWS);             // 512
    conv3x3_kernel<<<grid, THREADS>>>(X, W, B, out);
}